// round 4
// baseline (speedup 1.0000x reference)
#include <cuda_runtime.h>
#include <cuda_bf16.h>
#include <stdint.h>

#define DEVI __device__ __forceinline__

namespace {
constexpr int Bb = 4;
constexpr int Tt = 4096;
constexpr int Cc = 1024;
constexpr int Dd = 128;
constexpr int Mm = Bb * Tt;   // 16384
}

// ---------------- scratch (device globals; no allocations allowed) ----------
__device__ __align__(16) __nv_bfloat16 g_qhi[Mm * Dd];
__device__ __align__(16) __nv_bfloat16 g_qlo[Mm * Dd];
__device__ __align__(16) __nv_bfloat16 g_khi[Mm * Dd];
__device__ __align__(16) __nv_bfloat16 g_klo[Mm * Dd];
__device__ __align__(16) __nv_bfloat16 g_vhi[Mm * Dd];
__device__ __align__(16) __nv_bfloat16 g_vlo[Mm * Dd];

// ---------------- helpers ----------------------------------------------------
DEVI uint32_t su32(const void* p) { return (uint32_t)__cvta_generic_to_shared(p); }

DEVI void ldm4(uint32_t r[4], uint32_t a) {
    asm volatile("ldmatrix.sync.aligned.m8n8.x4.shared.b16 {%0,%1,%2,%3}, [%4];"
                 : "=r"(r[0]), "=r"(r[1]), "=r"(r[2]), "=r"(r[3]) : "r"(a));
}
DEVI void ldm4t(uint32_t r[4], uint32_t a) {
    asm volatile("ldmatrix.sync.aligned.m8n8.x4.trans.shared.b16 {%0,%1,%2,%3}, [%4];"
                 : "=r"(r[0]), "=r"(r[1]), "=r"(r[2]), "=r"(r[3]) : "r"(a));
}
DEVI void mma16816(float c[4], const uint32_t a[4], uint32_t b0, uint32_t b1) {
    asm volatile(
        "mma.sync.aligned.m16n8k16.row.col.f32.bf16.bf16.f32 "
        "{%0,%1,%2,%3}, {%4,%5,%6,%7}, {%8,%9}, {%0,%1,%2,%3};"
        : "+f"(c[0]), "+f"(c[1]), "+f"(c[2]), "+f"(c[3])
        : "r"(a[0]), "r"(a[1]), "r"(a[2]), "r"(a[3]), "r"(b0), "r"(b1));
}

DEVI uint32_t pack2(__nv_bfloat16 a, __nv_bfloat16 b) {
    __nv_bfloat162 t = __halves2bfloat162(a, b);
    return reinterpret_cast<uint32_t&>(t);
}
// split two fp32 into packed-bf16 hi word and packed-bf16 lo (residual) word
DEVI void split2(float a, float b, uint32_t& hi, uint32_t& lo) {
    __nv_bfloat16 ha = __float2bfloat16(a);
    __nv_bfloat16 hb = __float2bfloat16(b);
    hi = pack2(ha, hb);
    lo = pack2(__float2bfloat16(a - __bfloat162float(ha)),
               __float2bfloat16(b - __bfloat162float(hb)));
}

// ---------------- kernel 1: fused QKV projection -----------------------------
// grid (128, 3): 128 m-tiles of 128 rows; y selects Wq/Wk/Wv.
// Split-bf16 (hi/lo) 3-MMA emulation, fp32 accumulate.
__global__ __launch_bounds__(256) void qkv_kernel(
    const float* __restrict__ x,
    const float* __restrict__ Wq,
    const float* __restrict__ Wk,
    const float* __restrict__ Wv)
{
    __shared__ __align__(16) __nv_bfloat16 sAhi[128 * 40];
    __shared__ __align__(16) __nv_bfloat16 sAlo[128 * 40];
    __shared__ __align__(16) __nv_bfloat16 sBhi[32 * 136];
    __shared__ __align__(16) __nv_bfloat16 sBlo[32 * 136];

    const int sel = blockIdx.y;
    const float* W = (sel == 0) ? Wq : (sel == 1 ? Wk : Wv);
    __nv_bfloat16* Ohi = (sel == 0) ? g_qhi : (sel == 1 ? g_khi : g_vhi);
    __nv_bfloat16* Olo = (sel == 0) ? g_qlo : (sel == 1 ? g_klo : g_vlo);

    const int m0   = blockIdx.x * 128;
    const int tid  = threadIdx.x;
    const int warp = tid >> 5;
    const int lane = tid & 31;
    const int wm = warp & 3;   // 4 warps along m (32 rows each)
    const int wn = warp >> 2;  // 2 warps along n (64 cols each)
    const int g  = lane >> 2;
    const int tg = lane & 3;

    float acc[2][8][4] = {};

    for (int k0 = 0; k0 < Cc; k0 += 32) {
        // A tile 128x32 fp32 -> bf16 hi/lo in SMEM ([m][k], stride 40)
#pragma unroll
        for (int i = 0; i < 4; i++) {
            int idx = tid + i * 256;            // 0..1023
            int r = idx >> 3, c4 = (idx & 7) << 2;
            float4 v = *reinterpret_cast<const float4*>(&x[(size_t)(m0 + r) * Cc + k0 + c4]);
            float vv[4] = {v.x, v.y, v.z, v.w};
#pragma unroll
            for (int j = 0; j < 4; j++) {
                __nv_bfloat16 h = __float2bfloat16(vv[j]);
                sAhi[r * 40 + c4 + j] = h;
                sAlo[r * 40 + c4 + j] = __float2bfloat16(vv[j] - __bfloat162float(h));
            }
        }
        // B tile 32x128 fp32 -> bf16 hi/lo ([k][n], stride 136)
#pragma unroll
        for (int i = 0; i < 4; i++) {
            int idx = tid + i * 256;
            int r = idx >> 5, c4 = (idx & 31) << 2;
            float4 v = *reinterpret_cast<const float4*>(&W[(size_t)(k0 + r) * Dd + c4]);
            float vv[4] = {v.x, v.y, v.z, v.w};
#pragma unroll
            for (int j = 0; j < 4; j++) {
                __nv_bfloat16 h = __float2bfloat16(vv[j]);
                sBhi[r * 136 + c4 + j] = h;
                sBlo[r * 136 + c4 + j] = __float2bfloat16(vv[j] - __bfloat162float(h));
            }
        }
        __syncthreads();

#pragma unroll
        for (int ks = 0; ks < 2; ks++) {
            uint32_t ah[2][4], al[2][4];
#pragma unroll
            for (int mi = 0; mi < 2; mi++) {
                int arow = wm * 32 + mi * 16 + (lane & 15);
                int acol = ks * 16 + (lane >> 4) * 8;
                ldm4(ah[mi], su32(&sAhi[arow * 40 + acol]));
                ldm4(al[mi], su32(&sAlo[arow * 40 + acol]));
            }
#pragma unroll
            for (int nb = 0; nb < 4; nb++) {
                uint32_t bh[4], bl[4];
                int brow = ks * 16 + (lane & 7) + ((lane >> 3) & 1) * 8;
                int bcol = wn * 64 + nb * 16 + (lane >> 4) * 8;
                ldm4t(bh, su32(&sBhi[brow * 136 + bcol]));
                ldm4t(bl, su32(&sBlo[brow * 136 + bcol]));
#pragma unroll
                for (int sub = 0; sub < 2; sub++) {
#pragma unroll
                    for (int mi = 0; mi < 2; mi++) {
                        float* cc = acc[mi][nb * 2 + sub];
                        mma16816(cc, ah[mi], bh[2 * sub], bh[2 * sub + 1]);
                        mma16816(cc, ah[mi], bl[2 * sub], bl[2 * sub + 1]);
                        mma16816(cc, al[mi], bh[2 * sub], bh[2 * sub + 1]);
                    }
                }
            }
        }
        __syncthreads();
    }

    // epilogue: fp32 -> bf16 hi/lo pair stores
#pragma unroll
    for (int mi = 0; mi < 2; mi++) {
        int r0 = m0 + wm * 32 + mi * 16 + g;
#pragma unroll
        for (int nj = 0; nj < 8; nj++) {
            int col = wn * 64 + nj * 8 + 2 * tg;
            uint32_t hi, lo;
            split2(acc[mi][nj][0], acc[mi][nj][1], hi, lo);
            *reinterpret_cast<uint32_t*>(&Ohi[(size_t)r0 * Dd + col]) = hi;
            *reinterpret_cast<uint32_t*>(&Olo[(size_t)r0 * Dd + col]) = lo;
            split2(acc[mi][nj][2], acc[mi][nj][3], hi, lo);
            *reinterpret_cast<uint32_t*>(&Ohi[(size_t)(r0 + 8) * Dd + col]) = hi;
            *reinterpret_cast<uint32_t*>(&Olo[(size_t)(r0 + 8) * Dd + col]) = lo;
        }
    }
}

// ---------------- kernel 2: causal flash attention ----------------------------
// grid (64, 4): 64 q-tiles of 64 rows (reversed: longest work first), y = batch.
// 4 warps, each owns 16 q-rows. KV tiles of 32. Split-bf16 everywhere.
__global__ __launch_bounds__(128) void attn_kernel(float* __restrict__ out)
{
    __shared__ __align__(16) __nv_bfloat16 sKhi[32 * 136];
    __shared__ __align__(16) __nv_bfloat16 sKlo[32 * 136];
    __shared__ __align__(16) __nv_bfloat16 sVhi[32 * 136];
    __shared__ __align__(16) __nv_bfloat16 sVlo[32 * 136];

    const int bidx = blockIdx.y;
    const int q0   = (gridDim.x - 1 - blockIdx.x) * 64;
    const int tid  = threadIdx.x;
    const int warp = tid >> 5;
    const int lane = tid & 31;
    const int g  = lane >> 2;
    const int tg = lane & 3;
    const int wq = warp * 16;

    // preload Q fragments (hi/lo) straight from global (A-fragment layout)
    uint32_t qh[8][4], ql[8][4];
    {
        size_t bt = ((size_t)bidx * Tt + q0 + wq + g) * Dd;
#pragma unroll
        for (int kt = 0; kt < 8; kt++) {
            int c0 = kt * 16 + 2 * tg;
            qh[kt][0] = *reinterpret_cast<const uint32_t*>(&g_qhi[bt + c0]);
            qh[kt][1] = *reinterpret_cast<const uint32_t*>(&g_qhi[bt + 8 * Dd + c0]);
            qh[kt][2] = *reinterpret_cast<const uint32_t*>(&g_qhi[bt + c0 + 8]);
            qh[kt][3] = *reinterpret_cast<const uint32_t*>(&g_qhi[bt + 8 * Dd + c0 + 8]);
            ql[kt][0] = *reinterpret_cast<const uint32_t*>(&g_qlo[bt + c0]);
            ql[kt][1] = *reinterpret_cast<const uint32_t*>(&g_qlo[bt + 8 * Dd + c0]);
            ql[kt][2] = *reinterpret_cast<const uint32_t*>(&g_qlo[bt + c0 + 8]);
            ql[kt][3] = *reinterpret_cast<const uint32_t*>(&g_qlo[bt + 8 * Dd + c0 + 8]);
        }
    }

    float oacc[16][4] = {};
    float m_t = -1e30f, m_b = -1e30f, l_t = 0.f, l_b = 0.f;
    const float scale = 0.08838834764831845f;  // 1/sqrt(128)

    for (int s0 = 0; s0 < q0 + 64; s0 += 32) {
        __syncthreads();
        // load K/V tile (32 x 128, hi+lo) as uint4
        {
            size_t gb = ((size_t)bidx * Tt + s0) * Dd;
            const uint4* gkh = reinterpret_cast<const uint4*>(&g_khi[gb]);
            const uint4* gkl = reinterpret_cast<const uint4*>(&g_klo[gb]);
            const uint4* gvh = reinterpret_cast<const uint4*>(&g_vhi[gb]);
            const uint4* gvl = reinterpret_cast<const uint4*>(&g_vlo[gb]);
#pragma unroll
            for (int i = 0; i < 4; i++) {
                int idx = tid + i * 128;      // 32 rows * 16 uint4
                int r = idx >> 4, c = idx & 15;
                reinterpret_cast<uint4*>(&sKhi[r * 136])[c] = gkh[r * 16 + c];
                reinterpret_cast<uint4*>(&sKlo[r * 136])[c] = gkl[r * 16 + c];
                reinterpret_cast<uint4*>(&sVhi[r * 136])[c] = gvh[r * 16 + c];
                reinterpret_cast<uint4*>(&sVlo[r * 136])[c] = gvl[r * 16 + c];
            }
        }
        __syncthreads();

        // S = Q K^T (split-bf16, fp32 accum): 16x32 per warp
        float sacc[4][4] = {};
#pragma unroll
        for (int kt = 0; kt < 8; kt++) {
#pragma unroll
            for (int np = 0; np < 2; np++) {
                uint32_t kh[4], kl[4];
                int srow = np * 16 + ((lane >> 4) << 3) + (lane & 7);
                int kcol = kt * 16 + ((lane >> 3) & 1) * 8;
                ldm4(kh, su32(&sKhi[srow * 136 + kcol]));
                ldm4(kl, su32(&sKlo[srow * 136 + kcol]));
#pragma unroll
                for (int sub = 0; sub < 2; sub++) {
                    float* cc = sacc[np * 2 + sub];
                    mma16816(cc, qh[kt], kh[2 * sub], kh[2 * sub + 1]);
                    mma16816(cc, qh[kt], kl[2 * sub], kl[2 * sub + 1]);
                    mma16816(cc, ql[kt], kh[2 * sub], kh[2 * sub + 1]);
                }
            }
        }
#pragma unroll
        for (int nj = 0; nj < 4; nj++)
#pragma unroll
            for (int j = 0; j < 4; j++) sacc[nj][j] *= scale;

        // causal mask (only needed near the diagonal)
        const int rt = q0 + wq + g;
        if (s0 + 31 > q0 + wq) {
#pragma unroll
            for (int nj = 0; nj < 4; nj++) {
                int c = s0 + nj * 8 + 2 * tg;
                if (c     > rt)     sacc[nj][0] = -1e30f;
                if (c + 1 > rt)     sacc[nj][1] = -1e30f;
                if (c     > rt + 8) sacc[nj][2] = -1e30f;
                if (c + 1 > rt + 8) sacc[nj][3] = -1e30f;
            }
        }

        // online softmax: row max over 32 cols (4 threads per row -> quad shfl)
        float mx_t = -1e30f, mx_b = -1e30f;
#pragma unroll
        for (int nj = 0; nj < 4; nj++) {
            mx_t = fmaxf(mx_t, fmaxf(sacc[nj][0], sacc[nj][1]));
            mx_b = fmaxf(mx_b, fmaxf(sacc[nj][2], sacc[nj][3]));
        }
        mx_t = fmaxf(mx_t, __shfl_xor_sync(0xffffffffu, mx_t, 1));
        mx_t = fmaxf(mx_t, __shfl_xor_sync(0xffffffffu, mx_t, 2));
        mx_b = fmaxf(mx_b, __shfl_xor_sync(0xffffffffu, mx_b, 1));
        mx_b = fmaxf(mx_b, __shfl_xor_sync(0xffffffffu, mx_b, 2));

        float mN_t = fmaxf(m_t, mx_t), mN_b = fmaxf(m_b, mx_b);
        float cr_t = __expf(m_t - mN_t), cr_b = __expf(m_b - mN_b);
        m_t = mN_t; m_b = mN_b;

        float rs_t = 0.f, rs_b = 0.f;
#pragma unroll
        for (int nj = 0; nj < 4; nj++) {
            sacc[nj][0] = __expf(sacc[nj][0] - mN_t);
            sacc[nj][1] = __expf(sacc[nj][1] - mN_t);
            sacc[nj][2] = __expf(sacc[nj][2] - mN_b);
            sacc[nj][3] = __expf(sacc[nj][3] - mN_b);
            rs_t += sacc[nj][0] + sacc[nj][1];
            rs_b += sacc[nj][2] + sacc[nj][3];
        }
        rs_t += __shfl_xor_sync(0xffffffffu, rs_t, 1);
        rs_t += __shfl_xor_sync(0xffffffffu, rs_t, 2);
        rs_b += __shfl_xor_sync(0xffffffffu, rs_b, 1);
        rs_b += __shfl_xor_sync(0xffffffffu, rs_b, 2);
        l_t = l_t * cr_t + rs_t;
        l_b = l_b * cr_b + rs_b;

#pragma unroll
        for (int d = 0; d < 16; d++) {
            oacc[d][0] *= cr_t; oacc[d][1] *= cr_t;
            oacc[d][2] *= cr_b; oacc[d][3] *= cr_b;
        }

        // repack P (C-frag -> A-frag) with hi/lo split, then O += P V
        uint32_t ph[2][4], pl[2][4];
#pragma unroll
        for (int kb = 0; kb < 2; kb++) {
            split2(sacc[kb * 2][0],     sacc[kb * 2][1],     ph[kb][0], pl[kb][0]);
            split2(sacc[kb * 2][2],     sacc[kb * 2][3],     ph[kb][1], pl[kb][1]);
            split2(sacc[kb * 2 + 1][0], sacc[kb * 2 + 1][1], ph[kb][2], pl[kb][2]);
            split2(sacc[kb * 2 + 1][2], sacc[kb * 2 + 1][3], ph[kb][3], pl[kb][3]);
        }
#pragma unroll
        for (int kb = 0; kb < 2; kb++) {
            int vrow = kb * 16 + (lane & 7) + ((lane >> 3) & 1) * 8;
#pragma unroll
            for (int db = 0; db < 8; db++) {
                uint32_t vh[4], vl[4];
                int vcol = db * 16 + (lane >> 4) * 8;
                ldm4t(vh, su32(&sVhi[vrow * 136 + vcol]));
                ldm4t(vl, su32(&sVlo[vrow * 136 + vcol]));
#pragma unroll
                for (int sub = 0; sub < 2; sub++) {
                    float* cc = oacc[db * 2 + sub];
                    mma16816(cc, ph[kb], vh[2 * sub], vh[2 * sub + 1]);
                    mma16816(cc, pl[kb], vh[2 * sub], vh[2 * sub + 1]);
                    mma16816(cc, ph[kb], vl[2 * sub], vl[2 * sub + 1]);
                }
            }
        }
    }

    // epilogue: O / l -> out (fp32)
    float il_t = 1.f / l_t, il_b = 1.f / l_b;
    size_t ob = ((size_t)bidx * Tt + q0 + wq + g) * Dd;
#pragma unroll
    for (int d = 0; d < 16; d++) {
        int c = d * 8 + 2 * tg;
        float2 t0 = make_float2(oacc[d][0] * il_t, oacc[d][1] * il_t);
        float2 t1 = make_float2(oacc[d][2] * il_b, oacc[d][3] * il_b);
        *reinterpret_cast<float2*>(&out[ob + c])            = t0;
        *reinterpret_cast<float2*>(&out[ob + 8 * Dd + c])   = t1;
    }
}

// ---------------- launcher ----------------------------------------------------
extern "C" void kernel_launch(void* const* d_in, const int* in_sizes, int n_in,
                              void* d_out, int out_size) {
    const float* x  = (const float*)d_in[0];
    const float* Wq = (const float*)d_in[1];
    const float* Wk = (const float*)d_in[2];
    const float* Wv = (const float*)d_in[3];
    float* out = (float*)d_out;

    qkv_kernel<<<dim3(Mm / 128, 3), 256>>>(x, Wq, Wk, Wv);
    attn_kernel<<<dim3(Tt / 64, Bb), 128>>>(out);
}